// round 8
// baseline (speedup 1.0000x reference)
#include <cuda_runtime.h>
#include <cuda_fp16.h>
#include <math.h>

#define NB 4
#define DD 16
#define HH 512
#define WW 512
#define PLANE (HH*WW)
#define VOL (DD*PLANE)
#define TOT (NB*VOL)
#define C1F 0.0001f
#define C2F 0.0009f

// Gaussian weights (sigma=1.5, wsize=11) as literals -> FFMA-imm (rt_SMSP=1).
#define GW0 0.00102838f
#define GW1 0.00759875f
#define GW2 0.03600077f
#define GW3 0.10936069f
#define GW4 0.21300554f
#define GW5 0.26601173f

__device__ constexpr float gwt(int k) {
    return (k == 0 || k == 10) ? GW0 : (k == 1 || k == 9) ? GW1 :
           (k == 2 || k == 8)  ? GW2 : (k == 3 || k == 7) ? GW3 :
           (k == 4 || k == 6)  ? GW4 : GW5;
}
// Folded boundary weight: effective weight of source s for output d under
// clamped 11-tap blur over D=16.
__device__ constexpr float weff(int d, int s) {
    float a = 0.f;
    for (int k = 0; k < 11; k++) {
        int dd = d - 5 + k;
        dd = dd < 0 ? 0 : (dd > 15 ? 15 : dd);
        if (dd == s) a += gwt(k);
    }
    return a;
}

// Blurred fields, fp16: (p,g) packed, (p^2,g^2) packed, p*g scalar. [N*D,H,W]
__device__ __half2 g01[TOT];
__device__ __half2 g23[TOT];
__device__ __half  g4v[TOT];
// [0..3] per-n sum (p-g)^2 ; [4..7] per-n sum ssim_map. Zero at load; the
// fused finalizer re-zeroes after reading so each replay starts clean.
__device__ double g_acc[8];
__device__ unsigned int g_cnt;   // zero-init; reset by finalizer

__device__ __forceinline__ float blur11(const float* v) {
    float a;
    a = v[0]  * GW0;
    a = fmaf(v[1],  GW1, a);
    a = fmaf(v[2],  GW2, a);
    a = fmaf(v[3],  GW3, a);
    a = fmaf(v[4],  GW4, a);
    a = fmaf(v[5],  GW5, a);
    a = fmaf(v[6],  GW4, a);
    a = fmaf(v[7],  GW3, a);
    a = fmaf(v[8],  GW2, a);
    a = fmaf(v[9],  GW1, a);
    a = fmaf(v[10], GW0, a);
    return a;
}

// Wide (LDS.128/LDS.64) load of an 18-float window; base must be 16B-aligned.
__device__ __forceinline__ void load18(const float* base, float* v) {
    float4 a = *(const float4*)(base);
    float4 b = *(const float4*)(base + 4);
    float4 c = *(const float4*)(base + 8);
    float4 d = *(const float4*)(base + 12);
    float2 e = *(const float2*)(base + 16);
    v[0]=a.x; v[1]=a.y; v[2]=a.z; v[3]=a.w;
    v[4]=b.x; v[5]=b.y; v[6]=b.z; v[7]=b.w;
    v[8]=c.x; v[9]=c.y; v[10]=c.z; v[11]=c.w;
    v[12]=d.x; v[13]=d.y; v[14]=d.z; v[15]=d.w;
    v[16]=e.x; v[17]=e.y;
}

// Transposed tmp layout: column c (0..31), row r (0..41).
// Swizzle keeps W-pass STS conflict-free AND H-pass LDS.128 row-contiguous.
// All tidx(c, r0) bases with r0 multiple of 8 are multiples of 4 floats.
__device__ __forceinline__ int tidx(int c, int r) {
    return c * 44 + ((c >> 3) & 3) * 8 + r;
}
// Padded to a multiple of 4 floats so consecutive arrays stay 16B-aligned.
#define TSZ 1432

// Fused field-gen + W-blur + H-blur per (n,d) slice tile; PSNR fused.
__global__ __launch_bounds__(256) void blur2d_kernel(
    const float* __restrict__ pred, const float* __restrict__ gt)
{
    __shared__ __align__(16) float sp[42][44];
    __shared__ __align__(16) float sg[42][44];
    __shared__ __align__(16) float tx[TSZ];
    __shared__ __align__(16) float ty[TSZ];
    __shared__ __align__(16) float tz[TSZ];
    __shared__ float red[256];

    int z = blockIdx.z;
    int n = z >> 4;
    const float* pz = pred + (size_t)z * PLANE;
    const float* gz = gt   + (size_t)z * PLANE;
    int h0 = blockIdx.y * 32 - 5;
    int w0 = blockIdx.x * 32 - 5;
    int hb = blockIdx.y * 32, wb = blockIdx.x * 32;
    int tid = threadIdx.x;

    // ---- Load 42x42 tile (clamped = replicate pad) ----
    for (int i = tid; i < 42*42; i += 256) {
        int r = i / 42, c = i - r*42;
        int hh = min(max(h0 + r, 0), HH-1);
        int ww = min(max(w0 + c, 0), WW-1);
        sp[r][c] = pz[hh*WW + ww];
        sg[r][c] = gz[hh*WW + ww];
    }
    __syncthreads();

    // ---- PSNR partial over interior 32x32 ----
    float psum = 0.f;
    #pragma unroll
    for (int i = 0; i < 4; i++) {
        int j = tid + i*256;
        int r = 5 + (j >> 5), c = 5 + (j & 31);
        float d = sp[r][c] - sg[r][c];
        psum = fmaf(d, d, psum);
    }

    int rW = tid >> 2, chW = (tid & 3) * 8;   // W-pass coords (tid < 168)
    int hch = tid >> 5, cH = tid & 31;        // H-pass coords (tid < 128)

    // ======== W pass 1: p -> tx, g -> ty, p*g -> tz (sequential windows) ====
    if (tid < 168) {
        {
            float v[18]; load18(&sp[rW][chW], v);
            #pragma unroll
            for (int o = 0; o < 8; o++) tx[tidx(chW + o, rW)] = blur11(v + o);
        }
        {
            float v[18]; load18(&sg[rW][chW], v);
            #pragma unroll
            for (int o = 0; o < 8; o++) ty[tidx(chW + o, rW)] = blur11(v + o);
        }
        {
            float v[18], u[18];
            load18(&sp[rW][chW], v);
            load18(&sg[rW][chW], u);
            #pragma unroll
            for (int k = 0; k < 18; k++) v[k] *= u[k];
            #pragma unroll
            for (int o = 0; o < 8; o++) tz[tidx(chW + o, rW)] = blur11(v + o);
        }
    }
    __syncthreads();
    // ======== H pass 1: write g01 (half2) + g4v (half) ========
    if (tid < 128) {
        float xo[8], yo[8];
        {
            float v[18]; load18(&tx[tidx(cH, hch*8)], v);
            #pragma unroll
            for (int o = 0; o < 8; o++) xo[o] = blur11(v + o);
        }
        {
            float v[18]; load18(&ty[tidx(cH, hch*8)], v);
            #pragma unroll
            for (int o = 0; o < 8; o++) yo[o] = blur11(v + o);
        }
        __half2* o01 = &g01[(size_t)z * PLANE];
        #pragma unroll
        for (int o = 0; o < 8; o++) {
            int row = hb + hch*8 + o;
            o01[row*WW + wb + cH] = __floats2half2_rn(xo[o], yo[o]);
        }
        {
            float v[18]; load18(&tz[tidx(cH, hch*8)], v);
            __half* o4 = &g4v[(size_t)z * PLANE];
            #pragma unroll
            for (int o = 0; o < 8; o++) {
                int row = hb + hch*8 + o;
                o4[row*WW + wb + cH] = __float2half_rn(blur11(v + o));
            }
        }
    }
    __syncthreads();

    // ======== W pass 2: p^2 -> tx, g^2 -> ty ========
    if (tid < 168) {
        {
            float v[18]; load18(&sp[rW][chW], v);
            #pragma unroll
            for (int k = 0; k < 18; k++) v[k] *= v[k];
            #pragma unroll
            for (int o = 0; o < 8; o++) tx[tidx(chW + o, rW)] = blur11(v + o);
        }
        {
            float v[18]; load18(&sg[rW][chW], v);
            #pragma unroll
            for (int k = 0; k < 18; k++) v[k] *= v[k];
            #pragma unroll
            for (int o = 0; o < 8; o++) ty[tidx(chW + o, rW)] = blur11(v + o);
        }
    }
    __syncthreads();
    // ======== H pass 2: write g23 ========
    if (tid < 128) {
        float xo[8], yo[8];
        {
            float v[18]; load18(&tx[tidx(cH, hch*8)], v);
            #pragma unroll
            for (int o = 0; o < 8; o++) xo[o] = blur11(v + o);
        }
        {
            float v[18]; load18(&ty[tidx(cH, hch*8)], v);
            #pragma unroll
            for (int o = 0; o < 8; o++) yo[o] = blur11(v + o);
        }
        __half2* o23 = &g23[(size_t)z * PLANE];
        #pragma unroll
        for (int o = 0; o < 8; o++) {
            int row = hb + hch*8 + o;
            o23[row*WW + wb + cH] = __floats2half2_rn(xo[o], yo[o]);
        }
    }
    __syncthreads();

    // ---- PSNR block reduce ----
    red[tid] = psum;
    __syncthreads();
    #pragma unroll
    for (int s = 128; s > 0; s >>= 1) {
        if (tid < s) red[tid] += red[tid + s];
        __syncthreads();
    }
    if (tid == 0) atomicAdd(&g_acc[n], (double)red[0]);
}

#define SSIM_BLOCKS (NB * (PLANE/256))

// D-blur (folded boundary weights) + SSIM + reduction + fused finalizer.
__global__ __launch_bounds__(256) void ssim_d_kernel(float* out, int out_size) {
    int tid = threadIdx.x;
    int idx = blockIdx.x * 256 + tid;
    int n   = blockIdx.y;
    size_t base = (size_t)n * VOL + idx;

    float i0[16], i1[16], i2[16], i3[16], i4[16];
    #pragma unroll
    for (int d = 0; d < 16; d++) {
        size_t off = base + (size_t)d * PLANE;
        float2 a = __half22float2(g01[off]);
        float2 b = __half22float2(g23[off]);
        i0[d] = a.x; i1[d] = a.y;
        i2[d] = b.x; i3[d] = b.y;
        i4[d] = __half2float(g4v[off]);
    }

    float ssum = 0.f;
    #pragma unroll
    for (int d = 0; d < 16; d++) {
        float b0=0.f,b1=0.f,b2=0.f,b3=0.f,b4=0.f;
        const int lo = (d < 5) ? 0 : d - 5;
        const int hi = (d > 10) ? 15 : d + 5;
        #pragma unroll
        for (int s = lo; s <= hi; s++) {
            const float w = weff(d, s);   // literal after unroll
            b0 = fmaf(i0[s], w, b0);
            b1 = fmaf(i1[s], w, b1);
            b2 = fmaf(i2[s], w, b2);
            b3 = fmaf(i3[s], w, b3);
            b4 = fmaf(i4[s], w, b4);
        }
        float mu1 = b0, mu2 = b1;
        float mu1s = mu1*mu1, mu2s = mu2*mu2, mu12 = mu1*mu2;
        float s1 = b2 - mu1s, s2 = b3 - mu2s, s12 = b4 - mu12;
        float v1 = 2.f*s12 + C2F;
        float v2 = s1 + s2 + C2F;
        float num = (2.f*mu12 + C1F) * v1;
        float den = (mu1s + mu2s + C1F) * v2;
        ssum += __fdividef(num, den);
    }

    __shared__ float red[256];
    red[tid] = ssum;
    __syncthreads();
    #pragma unroll
    for (int s = 128; s > 0; s >>= 1) {
        if (tid < s) red[tid] += red[tid + s];
        __syncthreads();
    }
    if (tid == 0) {
        atomicAdd(&g_acc[4 + n], (double)red[0]);
        __threadfence();
        unsigned int done = atomicAdd(&g_cnt, 1u);
        if (done == SSIM_BLOCKS - 1) {
            // Last block: all g_acc contributions are visible. Finalize.
            float psnr = 0.f, ssim = 0.f;
            #pragma unroll
            for (int k = 0; k < NB; k++) {
                float mse = (float)(g_acc[k] / (double)VOL);
                psnr += 10.0f * log10f(1.0f / mse);
                ssim += (float)(g_acc[4 + k] / (double)VOL);
            }
            if (out_size > 0) out[0] = psnr;
            if (out_size > 1) out[1] = ssim;
            if (out_size > 2) out[2] = (float)NB;
            for (int i = 3; i < out_size; i++) out[i] = 0.f;
            // Restore invariants for next replay.
            for (int i = 0; i < 8; i++) g_acc[i] = 0.0;
            g_cnt = 0u;
        }
    }
}

extern "C" void kernel_launch(void* const* d_in, const int* in_sizes, int n_in,
                              void* d_out, int out_size) {
    const float* pred = (const float*)d_in[0];
    const float* gt   = (const float*)d_in[1];

    dim3 g1(WW/32, HH/32, NB*DD);
    blur2d_kernel<<<g1, 256>>>(pred, gt);

    dim3 g2(PLANE/256, NB);
    ssim_d_kernel<<<g2, 256>>>((float*)d_out, out_size);
}

// round 9
// speedup vs baseline: 1.5031x; 1.5031x over previous
#include <cuda_runtime.h>
#include <cuda_fp16.h>
#include <math.h>

#define NB 4
#define DD 16
#define HH 512
#define WW 512
#define PLANE (HH*WW)
#define VOL (DD*PLANE)
#define TOT (NB*VOL)
#define C1F 0.0001f
#define C2F 0.0009f

// Gaussian weights (sigma=1.5, wsize=11) as literals -> FFMA-imm (rt_SMSP=1).
#define GW0 0.00102838f
#define GW1 0.00759875f
#define GW2 0.03600077f
#define GW3 0.10936069f
#define GW4 0.21300554f
#define GW5 0.26601173f

// Blurred fields, fp16: (p,g) packed, (p^2,g^2) packed, p*g scalar. [N*D,H,W]
__device__ __half2 g01[TOT];
__device__ __half2 g23[TOT];
__device__ __half  g4v[TOT];
// [0..3] per-n sum (p-g)^2 ; [4..7] per-n sum ssim_map. Zero at load; the
// fused finalizer re-zeroes after reading so each replay starts clean.
__device__ double g_acc[8];
__device__ unsigned int g_cnt;   // zero-init; reset by finalizer

__device__ __forceinline__ float blur11(const float* v) {
    float a;
    a = v[0]  * GW0;
    a = fmaf(v[1],  GW1, a);
    a = fmaf(v[2],  GW2, a);
    a = fmaf(v[3],  GW3, a);
    a = fmaf(v[4],  GW4, a);
    a = fmaf(v[5],  GW5, a);
    a = fmaf(v[6],  GW4, a);
    a = fmaf(v[7],  GW3, a);
    a = fmaf(v[8],  GW2, a);
    a = fmaf(v[9],  GW1, a);
    a = fmaf(v[10], GW0, a);
    return a;
}

// Fused field-gen + W-blur + H-blur per (n,d) slice tile; PSNR fused.
// SoA scalar smem, strides chosen conflict-free (45 for tiles, 33 for tmp).
// (R5 configuration: regs 32, occ 96%, blur2d 154us — empirically best.)
__global__ __launch_bounds__(256) void blur2d_kernel(
    const float* __restrict__ pred, const float* __restrict__ gt)
{
    __shared__ float sp[42][45];   // p   (stride 45: odd -> conflict-free W reads)
    __shared__ float sg[42][45];   // g
    __shared__ float tx[42][33];   // tmp (stride 33 -> conflict-free STS/LDS)
    __shared__ float ty[42][33];
    __shared__ float red[256];

    int z = blockIdx.z;
    int n = z >> 4;
    const float* pz = pred + (size_t)z * PLANE;
    const float* gz = gt   + (size_t)z * PLANE;
    int h0 = blockIdx.y * 32 - 5;
    int w0 = blockIdx.x * 32 - 5;
    int hb = blockIdx.y * 32, wb = blockIdx.x * 32;
    int tid = threadIdx.x;

    // ---- Load 42x42 tile (clamped = replicate pad) ----
    for (int i = tid; i < 42*42; i += 256) {
        int r = i / 42, c = i - r*42;
        int hh = min(max(h0 + r, 0), HH-1);
        int ww = min(max(w0 + c, 0), WW-1);
        sp[r][c] = pz[hh*WW + ww];
        sg[r][c] = gz[hh*WW + ww];
    }
    __syncthreads();

    // ---- PSNR partial over interior 32x32 ----
    float psum = 0.f;
    #pragma unroll
    for (int i = 0; i < 4; i++) {
        int j = tid + i*256;
        int r = 5 + (j >> 5), c = 5 + (j & 31);
        float d = sp[r][c] - sg[r][c];
        psum = fmaf(d, d, psum);
    }

    int rW = tid >> 2, chW = (tid & 3) * 8;   // W-pass coords (tid < 168)
    int hch = tid >> 5, cH = tid & 31;        // H-pass coords (tid < 128)

    // ======== Pass A: {p, g} ========
    if (tid < 168) {
        float vx[18], vy[18];
        #pragma unroll
        for (int k = 0; k < 18; k++) { vx[k] = sp[rW][chW + k]; vy[k] = sg[rW][chW + k]; }
        #pragma unroll
        for (int o = 0; o < 8; o++) {
            tx[rW][chW + o] = blur11(vx + o);
            ty[rW][chW + o] = blur11(vy + o);
        }
    }
    __syncthreads();
    if (tid < 128) {
        float vx[18], vy[18];
        #pragma unroll
        for (int k = 0; k < 18; k++) { vx[k] = tx[hch*8 + k][cH]; vy[k] = ty[hch*8 + k][cH]; }
        __half2* o01 = &g01[(size_t)z * PLANE];
        #pragma unroll
        for (int o = 0; o < 8; o++) {
            int row = hb + hch*8 + o;
            o01[row*WW + wb + cH] = __floats2half2_rn(blur11(vx + o), blur11(vy + o));
        }
    }
    __syncthreads();

    // ======== Pass B: {p^2, g^2} (squared on load; no extra tiles) ========
    if (tid < 168) {
        float vx[18], vy[18];
        #pragma unroll
        for (int k = 0; k < 18; k++) {
            float a = sp[rW][chW + k], b = sg[rW][chW + k];
            vx[k] = a * a; vy[k] = b * b;
        }
        #pragma unroll
        for (int o = 0; o < 8; o++) {
            tx[rW][chW + o] = blur11(vx + o);
            ty[rW][chW + o] = blur11(vy + o);
        }
    }
    __syncthreads();
    if (tid < 128) {
        float vx[18], vy[18];
        #pragma unroll
        for (int k = 0; k < 18; k++) { vx[k] = tx[hch*8 + k][cH]; vy[k] = ty[hch*8 + k][cH]; }
        __half2* o23 = &g23[(size_t)z * PLANE];
        #pragma unroll
        for (int o = 0; o < 8; o++) {
            int row = hb + hch*8 + o;
            o23[row*WW + wb + cH] = __floats2half2_rn(blur11(vx + o), blur11(vy + o));
        }
    }
    __syncthreads();

    // ======== Pass C: p*g ========
    if (tid < 168) {
        float v[18];
        #pragma unroll
        for (int k = 0; k < 18; k++) v[k] = sp[rW][chW + k] * sg[rW][chW + k];
        #pragma unroll
        for (int o = 0; o < 8; o++) tx[rW][chW + o] = blur11(v + o);
    }
    __syncthreads();
    if (tid < 128) {
        float v[18];
        #pragma unroll
        for (int k = 0; k < 18; k++) v[k] = tx[hch*8 + k][cH];
        __half* o4 = &g4v[(size_t)z * PLANE];
        #pragma unroll
        for (int o = 0; o < 8; o++) {
            int row = hb + hch*8 + o;
            o4[row*WW + wb + cH] = __float2half_rn(blur11(v + o));
        }
    }
    __syncthreads();

    // ---- PSNR block reduce ----
    red[tid] = psum;
    __syncthreads();
    #pragma unroll
    for (int s = 128; s > 0; s >>= 1) {
        if (tid < s) red[tid] += red[tid + s];
        __syncthreads();
    }
    if (tid == 0) atomicAdd(&g_acc[n], (double)red[0]);
}

#define SSIM_BLOCKS (NB * (PLANE/256))

// D-blur in registers (D=16, clamped) + SSIM pointwise + reduction,
// with the finalizer fused into the last block (saves one launch).
__global__ __launch_bounds__(256) void ssim_d_kernel(float* out, int out_size) {
    int tid = threadIdx.x;
    int idx = blockIdx.x * 256 + tid;
    int n   = blockIdx.y;
    size_t base = (size_t)n * VOL + idx;

    float i0[16], i1[16], i2[16], i3[16], i4[16];
    #pragma unroll
    for (int d = 0; d < 16; d++) {
        size_t off = base + (size_t)d * PLANE;
        float2 a = __half22float2(g01[off]);
        float2 b = __half22float2(g23[off]);
        i0[d] = a.x; i1[d] = a.y;
        i2[d] = b.x; i3[d] = b.y;
        i4[d] = __half2float(g4v[off]);
    }

    const float wq[11] = {GW0,GW1,GW2,GW3,GW4,GW5,GW4,GW3,GW2,GW1,GW0};
    float ssum = 0.f;
    #pragma unroll
    for (int d = 0; d < 16; d++) {
        float b0=0.f,b1=0.f,b2=0.f,b3=0.f,b4=0.f;
        #pragma unroll
        for (int k = 0; k < 11; k++) {
            int dd = d - 5 + k;
            dd = dd < 0 ? 0 : (dd > 15 ? 15 : dd);   // compile-time after unroll
            float w = wq[k];                          // literal after unroll
            b0 = fmaf(i0[dd], w, b0);
            b1 = fmaf(i1[dd], w, b1);
            b2 = fmaf(i2[dd], w, b2);
            b3 = fmaf(i3[dd], w, b3);
            b4 = fmaf(i4[dd], w, b4);
        }
        float mu1 = b0, mu2 = b1;
        float mu1s = mu1*mu1, mu2s = mu2*mu2, mu12 = mu1*mu2;
        float s1 = b2 - mu1s, s2 = b3 - mu2s, s12 = b4 - mu12;
        float v1 = 2.f*s12 + C2F;
        float v2 = s1 + s2 + C2F;
        float num = (2.f*mu12 + C1F) * v1;
        float den = (mu1s + mu2s + C1F) * v2;
        ssum += __fdividef(num, den);
    }

    __shared__ float red[256];
    red[tid] = ssum;
    __syncthreads();
    #pragma unroll
    for (int s = 128; s > 0; s >>= 1) {
        if (tid < s) red[tid] += red[tid + s];
        __syncthreads();
    }
    if (tid == 0) {
        atomicAdd(&g_acc[4 + n], (double)red[0]);
        __threadfence();
        unsigned int done = atomicAdd(&g_cnt, 1u);
        if (done == SSIM_BLOCKS - 1) {
            // Last block: all g_acc contributions are visible. Finalize.
            float psnr = 0.f, ssim = 0.f;
            #pragma unroll
            for (int k = 0; k < NB; k++) {
                float mse = (float)(g_acc[k] / (double)VOL);
                psnr += 10.0f * log10f(1.0f / mse);
                ssim += (float)(g_acc[4 + k] / (double)VOL);
            }
            if (out_size > 0) out[0] = psnr;
            if (out_size > 1) out[1] = ssim;
            if (out_size > 2) out[2] = (float)NB;
            for (int i = 3; i < out_size; i++) out[i] = 0.f;
            // Restore invariants for next replay.
            for (int i = 0; i < 8; i++) g_acc[i] = 0.0;
            g_cnt = 0u;
        }
    }
}

extern "C" void kernel_launch(void* const* d_in, const int* in_sizes, int n_in,
                              void* d_out, int out_size) {
    const float* pred = (const float*)d_in[0];
    const float* gt   = (const float*)d_in[1];

    dim3 g1(WW/32, HH/32, NB*DD);
    blur2d_kernel<<<g1, 256>>>(pred, gt);

    dim3 g2(PLANE/256, NB);
    ssim_d_kernel<<<g2, 256>>>((float*)d_out, out_size);
}

// round 10
// speedup vs baseline: 1.7285x; 1.1499x over previous
#include <cuda_runtime.h>
#include <cuda_fp16.h>
#include <math.h>

#define NB 4
#define DD 16
#define HH 512
#define WW 512
#define PLANE (HH*WW)
#define VOL (DD*PLANE)
#define TOT (NB*VOL)
#define C1F 0.0001f
#define C2F 0.0009f

// Gaussian weights (sigma=1.5, wsize=11) as literals -> FFMA-imm (rt_SMSP=1).
#define GW0 0.00102838f
#define GW1 0.00759875f
#define GW2 0.03600077f
#define GW3 0.10936069f
#define GW4 0.21300554f
#define GW5 0.26601173f

// Blurred fields, fp16, derived basis: A=p+g, B=p-g.
// gAB  = half2( blur(A),  blur(B)  )
// gSQ  = half2( blur(A^2), blur(B^2) )
__device__ __half2 gAB[TOT];
__device__ __half2 gSQ[TOT];
// [0..3] per-n sum B^2 = (p-g)^2 ; [4..7] per-n sum ssim_map. Zero at load;
// the fused finalizer re-zeroes after reading so each replay starts clean.
__device__ double g_acc[8];
__device__ unsigned int g_cnt;   // zero-init; reset by finalizer

__device__ __forceinline__ float blur11(const float* v) {
    float a;
    a = v[0]  * GW0;
    a = fmaf(v[1],  GW1, a);
    a = fmaf(v[2],  GW2, a);
    a = fmaf(v[3],  GW3, a);
    a = fmaf(v[4],  GW4, a);
    a = fmaf(v[5],  GW5, a);
    a = fmaf(v[6],  GW4, a);
    a = fmaf(v[7],  GW3, a);
    a = fmaf(v[8],  GW2, a);
    a = fmaf(v[9],  GW1, a);
    a = fmaf(v[10], GW0, a);
    return a;
}

// Fused field-gen + W-blur + H-blur per (n,d) slice tile; PSNR fused.
// R5-proven structure (regs 32, occ 96%), now 2 field passes instead of 3.
__global__ __launch_bounds__(256) void blur2d_kernel(
    const float* __restrict__ pred, const float* __restrict__ gt)
{
    __shared__ float sA[42][45];   // A = p+g (stride 45: conflict-free W reads)
    __shared__ float sB[42][45];   // B = p-g
    __shared__ float tx[42][33];   // tmp (stride 33 -> conflict-free STS/LDS)
    __shared__ float ty[42][33];
    __shared__ float red[256];

    int z = blockIdx.z;
    int n = z >> 4;
    const float* pz = pred + (size_t)z * PLANE;
    const float* gz = gt   + (size_t)z * PLANE;
    int h0 = blockIdx.y * 32 - 5;
    int w0 = blockIdx.x * 32 - 5;
    int hb = blockIdx.y * 32, wb = blockIdx.x * 32;
    int tid = threadIdx.x;

    // ---- Load 42x42 tile (clamped = replicate pad), basis transform ----
    for (int i = tid; i < 42*42; i += 256) {
        int r = i / 42, c = i - r*42;
        int hh = min(max(h0 + r, 0), HH-1);
        int ww = min(max(w0 + c, 0), WW-1);
        float p = pz[hh*WW + ww];
        float g = gz[hh*WW + ww];
        sA[r][c] = p + g;
        sB[r][c] = p - g;
    }
    __syncthreads();

    // ---- PSNR partial over interior 32x32: (p-g)^2 = B^2 ----
    float psum = 0.f;
    #pragma unroll
    for (int i = 0; i < 4; i++) {
        int j = tid + i*256;
        int r = 5 + (j >> 5), c = 5 + (j & 31);
        float d = sB[r][c];
        psum = fmaf(d, d, psum);
    }

    int rW = tid >> 2, chW = (tid & 3) * 8;   // W-pass coords (tid < 168)
    int hch = tid >> 5, cH = tid & 31;        // H-pass coords (tid < 128)

    // ======== Pass 1: {A, B} ========
    if (tid < 168) {
        float vx[18], vy[18];
        #pragma unroll
        for (int k = 0; k < 18; k++) { vx[k] = sA[rW][chW + k]; vy[k] = sB[rW][chW + k]; }
        #pragma unroll
        for (int o = 0; o < 8; o++) {
            tx[rW][chW + o] = blur11(vx + o);
            ty[rW][chW + o] = blur11(vy + o);
        }
    }
    __syncthreads();
    if (tid < 128) {
        float vx[18], vy[18];
        #pragma unroll
        for (int k = 0; k < 18; k++) { vx[k] = tx[hch*8 + k][cH]; vy[k] = ty[hch*8 + k][cH]; }
        __half2* oAB = &gAB[(size_t)z * PLANE];
        #pragma unroll
        for (int o = 0; o < 8; o++) {
            int row = hb + hch*8 + o;
            oAB[row*WW + wb + cH] = __floats2half2_rn(blur11(vx + o), blur11(vy + o));
        }
    }
    __syncthreads();

    // ======== Pass 2: {A^2, B^2} (squared on load) ========
    if (tid < 168) {
        float vx[18], vy[18];
        #pragma unroll
        for (int k = 0; k < 18; k++) {
            float a = sA[rW][chW + k], b = sB[rW][chW + k];
            vx[k] = a * a; vy[k] = b * b;
        }
        #pragma unroll
        for (int o = 0; o < 8; o++) {
            tx[rW][chW + o] = blur11(vx + o);
            ty[rW][chW + o] = blur11(vy + o);
        }
    }
    __syncthreads();
    if (tid < 128) {
        float vx[18], vy[18];
        #pragma unroll
        for (int k = 0; k < 18; k++) { vx[k] = tx[hch*8 + k][cH]; vy[k] = ty[hch*8 + k][cH]; }
        __half2* oSQ = &gSQ[(size_t)z * PLANE];
        #pragma unroll
        for (int o = 0; o < 8; o++) {
            int row = hb + hch*8 + o;
            oSQ[row*WW + wb + cH] = __floats2half2_rn(blur11(vx + o), blur11(vy + o));
        }
    }
    __syncthreads();

    // ---- PSNR block reduce ----
    red[tid] = psum;
    __syncthreads();
    #pragma unroll
    for (int s = 128; s > 0; s >>= 1) {
        if (tid < s) red[tid] += red[tid + s];
        __syncthreads();
    }
    if (tid == 0) atomicAdd(&g_acc[n], (double)red[0]);
}

#define SSIM_BLOCKS (NB * (PLANE/256))

// D-blur in registers (D=16, clamped), 4 fields, + SSIM + reduction,
// with the finalizer fused into the last block.
__global__ __launch_bounds__(256) void ssim_d_kernel(float* out, int out_size) {
    int tid = threadIdx.x;
    int idx = blockIdx.x * 256 + tid;
    int n   = blockIdx.y;
    size_t base = (size_t)n * VOL + idx;

    float iA[16], iB[16], iA2[16], iB2[16];
    #pragma unroll
    for (int d = 0; d < 16; d++) {
        size_t off = base + (size_t)d * PLANE;
        float2 a = __half22float2(gAB[off]);
        float2 b = __half22float2(gSQ[off]);
        iA[d]  = a.x; iB[d]  = a.y;
        iA2[d] = b.x; iB2[d] = b.y;
    }

    const float wq[11] = {GW0,GW1,GW2,GW3,GW4,GW5,GW4,GW3,GW2,GW1,GW0};
    float ssum = 0.f;
    #pragma unroll
    for (int d = 0; d < 16; d++) {
        float mA=0.f, mB=0.f, eA=0.f, eB=0.f;
        #pragma unroll
        for (int k = 0; k < 11; k++) {
            int dd = d - 5 + k;
            dd = dd < 0 ? 0 : (dd > 15 ? 15 : dd);   // compile-time after unroll
            float w = wq[k];                          // literal after unroll
            mA = fmaf(iA[dd],  w, mA);
            mB = fmaf(iB[dd],  w, mB);
            eA = fmaf(iA2[dd], w, eA);
            eB = fmaf(iB2[dd], w, eB);
        }
        // Recover SSIM terms from the (A,B) basis:
        float mA2 = mA*mA, mB2 = mB*mB;
        float mu12 = 0.25f * (mA2 - mB2);       // mu1*mu2
        float musq = 0.5f  * (mA2 + mB2);       // mu1^2 + mu2^2
        float Epg  = 0.25f * (eA - eB);         // E[p*g]
        float Esq  = 0.5f  * (eA + eB);         // E[p^2] + E[g^2]
        float s12  = Epg - mu12;
        float s1s2 = Esq - musq;
        float v1 = 2.f*s12 + C2F;
        float v2 = s1s2 + C2F;
        float num = (2.f*mu12 + C1F) * v1;
        float den = (musq + C1F) * v2;
        ssum += __fdividef(num, den);
    }

    __shared__ float red[256];
    red[tid] = ssum;
    __syncthreads();
    #pragma unroll
    for (int s = 128; s > 0; s >>= 1) {
        if (tid < s) red[tid] += red[tid + s];
        __syncthreads();
    }
    if (tid == 0) {
        atomicAdd(&g_acc[4 + n], (double)red[0]);
        __threadfence();
        unsigned int done = atomicAdd(&g_cnt, 1u);
        if (done == SSIM_BLOCKS - 1) {
            // Last block: all g_acc contributions are visible. Finalize.
            float psnr = 0.f, ssim = 0.f;
            #pragma unroll
            for (int k = 0; k < NB; k++) {
                float mse = (float)(g_acc[k] / (double)VOL);
                psnr += 10.0f * log10f(1.0f / mse);
                ssim += (float)(g_acc[4 + k] / (double)VOL);
            }
            if (out_size > 0) out[0] = psnr;
            if (out_size > 1) out[1] = ssim;
            if (out_size > 2) out[2] = (float)NB;
            for (int i = 3; i < out_size; i++) out[i] = 0.f;
            // Restore invariants for next replay.
            for (int i = 0; i < 8; i++) g_acc[i] = 0.0;
            g_cnt = 0u;
        }
    }
}

extern "C" void kernel_launch(void* const* d_in, const int* in_sizes, int n_in,
                              void* d_out, int out_size) {
    const float* pred = (const float*)d_in[0];
    const float* gt   = (const float*)d_in[1];

    dim3 g1(WW/32, HH/32, NB*DD);
    blur2d_kernel<<<g1, 256>>>(pred, gt);

    dim3 g2(PLANE/256, NB);
    ssim_d_kernel<<<g2, 256>>>((float*)d_out, out_size);
}